// round 15
// baseline (speedup 1.0000x reference)
#include <cuda_runtime.h>
#include <cuda_fp16.h>

// CircularNN R14: R13 main kernel (parity-matched feature pairing, S=32,
// NT=512, 2 CTAs/SM, PADH2=786, HFMA2 taps, MUFU.TANH gelu) with prep split
// into two wide parallel kernels (rank: 54 blocks; build: 784 threads) to
// remove the ~10us single-block prep serialization seen in R13.

#define D      784
#define PADH2  786
#define S      32
#define NPAIR  16
#define NW     16
#define NT     512
#define NCLS   10
#define NFP    392

typedef unsigned long long ull;

// ---- packed records (slot-indexed) + prep scratch ----
__device__ uint4    g_r1[D];
__device__ uint4    g_r2a[D], g_r2b[D];
__device__ uint4    g_i3[D],  g_w3a[D], g_w3b[D];
__device__ unsigned g_b3[D];
__device__ unsigned short g_rank[3 * D];
__device__ int            g_cnt[3][2][9];

__device__ __forceinline__ unsigned duph(float w) {
    unsigned s = __half_as_ushort(__float2half_rn(w));
    return s | (s << 16);
}
__device__ __forceinline__ unsigned h16(float w) {
    return (unsigned)__half_as_ushort(__float2half_rn(w));
}
__device__ __forceinline__ __half2 u2h(unsigned u) {
    return *reinterpret_cast<const __half2*>(&u);
}

// ---- prep stage 1: per-(layer,class,bucket) deterministic ranks ----
__global__ void prep_rank(const int* __restrict__ idx1,
                          const int* __restrict__ idx2,
                          const int* __restrict__ idx3)
{
    const int combo = blockIdx.x;          // 0..53
    const int l   = combo / 18;
    const int rem = combo % 18;
    const int cls = rem / 9;
    const int a   = rem % 9;
    const int Ks[3] = {2, 4, 8};
    const int* idxs[3] = {idx1, idx2, idx3};
    const int K = Ks[l];
    const int lane = threadIdx.x;

    int running = 0;
    for (int base = 0; base < D; base += 32) {
        int f = base + lane;
        int bucket = 0;
        if (f < D) {
            for (int t = 0; t < K; ++t) bucket += ((idxs[l][f * K + t] & 1) == 0);
        }
        bool in = (f < D) && ((f & 1) == cls) && (bucket == a);
        unsigned mask = __ballot_sync(0xffffffffu, in);
        if (in) g_rank[l * D + f] = (unsigned short)(running + __popc(mask & ((1u << lane) - 1u)));
        running += __popc(mask);
    }
    if (lane == 0) g_cnt[l][cls][a] = running;
}

// ---- prep stage 2: build slot-indexed records ----
__global__ void prep_build(const int* __restrict__ idx1, const float* __restrict__ w1, const float* __restrict__ b1,
                           const int* __restrict__ idx2, const float* __restrict__ w2, const float* __restrict__ b2,
                           const int* __restrict__ idx3, const float* __restrict__ w3, const float* __restrict__ b3)
{
    const int f = blockIdx.x * blockDim.x + threadIdx.x;
    if (f >= D) return;
    const int cls = f & 1;
    const int Ks[3] = {2, 4, 8};
    const int* idxs[3] = {idx1, idx2, idx3};

    #pragma unroll
    for (int l = 0; l < 3; ++l) {
        const int K = Ks[l];
        int a = 0;
        for (int t = 0; t < K; ++t) a += ((idxs[l][f * K + t] & 1) == 0);
        const int r = g_rank[l * D + f];

        // prefix bases (redundant per-thread; <=9 iterations)
        int M[9], PB[9], LB0[9], LB1[9], Mtot = 0, lb0 = 0, lb1 = 0;
        for (int b = 0; b <= K; ++b) {
            int m = min(g_cnt[l][0][b], g_cnt[l][1][K - b]);
            M[b] = m; PB[b] = Mtot; Mtot += m;
            LB0[b] = lb0; lb0 += g_cnt[l][0][b] - m;
        }
        for (int b = 0; b <= K; ++b) {
            LB1[b] = lb1; lb1 += g_cnt[l][1][b] - M[K - b];
        }

        int q;
        if (cls == 0) {
            int m = M[a];
            q = (r < m) ? (PB[a] + r) : (Mtot + LB0[a] + (r - m));
        } else {
            int m = M[K - a];
            q = (r < m) ? (PB[K - a] + r) : (Mtot + LB1[a] + (r - m));
        }
        const int slot = 2 * q + cls;

        // ordered taps: cls0 -> even-parity first; cls1 -> odd-parity first
        int ord[8];
        {
            int n = 0;
            int want = (cls == 0) ? 0 : 1;
            for (int pass = 0; pass < 2; ++pass)
                for (int t = 0; t < K; ++t) {
                    int par = idxs[l][f * K + t] & 1;
                    if (par == ((pass == 0) ? want : (want ^ 1))) ord[n++] = t;
                }
        }
        const unsigned outoff = (unsigned)(f * 4);

        if (l == 0) {
            unsigned j0 = (unsigned)idx1[2*f + ord[0]] * 4u;
            unsigned j1 = (unsigned)idx1[2*f + ord[1]] * 4u;
            uint4 rr;
            rr.x = j0 | (j1 << 16);
            rr.y = duph(w1[2*f + ord[0]]);
            rr.z = duph(w1[2*f + ord[1]]);
            rr.w = h16(b1[f]) | (outoff << 16);
            g_r1[slot] = rr;
        } else if (l == 1) {
            unsigned j[4];
            for (int t = 0; t < 4; ++t) j[t] = (unsigned)idx2[4*f + ord[t]] * 4u;
            uint4 A, Bv;
            A.x = j[0] | (j[1] << 16);
            A.y = j[2] | (j[3] << 16);
            A.z = duph(w2[4*f + ord[0]]);
            A.w = duph(w2[4*f + ord[1]]);
            Bv.x = duph(w2[4*f + ord[2]]);
            Bv.y = duph(w2[4*f + ord[3]]);
            Bv.z = duph(b2[f]);
            Bv.w = outoff;
            g_r2a[slot] = A;
            g_r2b[slot] = Bv;
        } else {
            unsigned j[8];
            for (int t = 0; t < 8; ++t) j[t] = (unsigned)idx3[8*f + ord[t]] * 4u;
            uint4 I, Wa, Wb;
            I.x = j[0] | (j[1] << 16);  I.y = j[2] | (j[3] << 16);
            I.z = j[4] | (j[5] << 16);  I.w = j[6] | (j[7] << 16);
            Wa.x = duph(w3[8*f + ord[0]]); Wa.y = duph(w3[8*f + ord[1]]);
            Wa.z = duph(w3[8*f + ord[2]]); Wa.w = duph(w3[8*f + ord[3]]);
            Wb.x = duph(w3[8*f + ord[4]]); Wb.y = duph(w3[8*f + ord[5]]);
            Wb.z = duph(w3[8*f + ord[6]]); Wb.w = duph(w3[8*f + ord[7]]);
            g_i3[slot] = I;  g_w3a[slot] = Wa;  g_w3b[slot] = Wb;
            g_b3[slot] = h16(b3[f]) | (outoff << 16);
        }
    }
}

// ---- packed f32x2 helpers ----
__device__ __forceinline__ ull pack2(float a, float b) {
    ull r; asm("mov.b64 %0, {%1, %2};" : "=l"(r) : "f"(a), "f"(b)); return r;
}
__device__ __forceinline__ void unpack2(ull v, float& a, float& b) {
    asm("mov.b64 {%0, %1}, %2;" : "=f"(a), "=f"(b) : "l"(v));
}
#define FMA2(d,a,b,c) asm("fma.rn.f32x2 %0, %1, %2, %3;" : "=l"(d) : "l"(a), "l"(b), "l"(c))
#define MUL2(d,a,b)   asm("mul.rn.f32x2 %0, %1, %2;"     : "=l"(d) : "l"(a), "l"(b))

__device__ __forceinline__ __half2 gelu2(float ax, float ay) {
    const ull C_A    = pack2(0.7978845608f, 0.7978845608f);
    const ull C_B    = pack2(0.0356774081f, 0.0356774081f);
    const ull C_HALF = pack2(0.5f, 0.5f);
    ull X = pack2(ax, ay);
    ull T; MUL2(T, X, X);
    ull V; FMA2(V, T, C_B, C_A);
    MUL2(V, V, X);
    float vx, vy; unpack2(V, vx, vy);
    float tx, ty;
    asm("tanh.approx.f32 %0, %1;" : "=f"(tx) : "f"(vx));
    asm("tanh.approx.f32 %0, %1;" : "=f"(ty) : "f"(vy));
    ull TH = pack2(tx, ty);
    ull XH; MUL2(XH, X, C_HALF);
    ull O;  FMA2(O, XH, TH, XH);
    float ox, oy; unpack2(O, ox, oy);
    return __floats2half2_rn(ox, oy);
}

#define LH2(off) (*(const __half2*)(sb + (off)))

extern __shared__ __align__(16) char smem_raw[];

__global__ __launch_bounds__(NT, 2)
void circnn_kernel(const float* __restrict__ x,
                   const float* __restrict__ fc_w, const float* __restrict__ fc_b,
                   float* __restrict__ out, int B)
{
    __half2* bufA = (__half2*)smem_raw;          // NPAIR*PADH2 half2 = 50,304 B
    __half2* bufB = bufA + NPAIR * PADH2;
    float*   part = (float*)smem_raw;            // alias bufA after layer3
    float*   lgts = part + NW * S * NCLS;

    const int tid  = threadIdx.x;
    const int lane = tid & 31;
    const int warp = tid >> 5;
    const int p    = lane & 15;
    const int fo   = lane >> 4;
    const long base = (long)blockIdx.x * S;

    // --- input: warp w owns sample pair w; STS.64 (rows 8B-aligned) ---
    {
        const long s0 = base + 2 * warp;
        const float4* r0 = (const float4*)(x + s0 * (long)D);
        const float4* r1 = (const float4*)(x + (s0 + 1) * (long)D);
        uint2* drow = (uint2*)((char*)smem_raw + (warp * PADH2) * 4);
        for (int k = lane; k < D / 4; k += 32) {
            float4 a = __ldg(r0 + k);
            float4 b = __ldg(r1 + k);
            __half2 h0 = __floats2half2_rn(a.x, b.x);
            __half2 h1 = __floats2half2_rn(a.y, b.y);
            __half2 h2 = __floats2half2_rn(a.z, b.z);
            __half2 h3 = __floats2half2_rn(a.w, b.w);
            uint2 v0, v1;
            v0.x = *(unsigned*)&h0;  v0.y = *(unsigned*)&h1;
            v1.x = *(unsigned*)&h2;  v1.y = *(unsigned*)&h3;
            drow[2 * k]     = v0;
            drow[2 * k + 1] = v1;
        }
    }
    __syncthreads();

    // ---- layer 1 (K=2): parity-matched slots ----
    {
        const char* sb = (const char*)(bufA + p * PADH2);
        char*       db = (char*)(bufB + p * PADH2);
        #pragma unroll 4
        for (int pb = warp; pb < NFP; pb += NW) {
            const int slot = 2 * pb + fo;
            uint4 r = __ldg(g_r1 + slot);
            __half2 acc = __half2half2(__ushort_as_half((unsigned short)(r.w & 0xFFFFu)));
            acc = __hfma2(u2h(r.y), LH2(r.x & 0xFFFFu), acc);
            acc = __hfma2(u2h(r.z), LH2(r.x >> 16), acc);
            float2 a = __half22float2(acc);
            *(__half2*)(db + (r.w >> 16)) = gelu2(a.x, a.y);
        }
    }
    __syncthreads();

    // ---- layer 2 (K=4) ----
    {
        const char* sb = (const char*)(bufB + p * PADH2);
        char*       db = (char*)(bufA + p * PADH2);
        #pragma unroll 4
        for (int pb = warp; pb < NFP; pb += NW) {
            const int slot = 2 * pb + fo;
            uint4 A  = __ldg(&g_r2a[slot]);
            uint4 Bv = __ldg(&g_r2b[slot]);
            __half2 acc = u2h(Bv.z);
            __half2 t   = __hmul2(u2h(A.w),  LH2(A.x >> 16));
            acc = __hfma2(u2h(A.z),  LH2(A.x & 0xFFFFu), acc);
            t   = __hfma2(u2h(Bv.y), LH2(A.y >> 16), t);
            acc = __hfma2(u2h(Bv.x), LH2(A.y & 0xFFFFu), acc);
            acc = __hadd2(acc, t);
            float2 a = __half22float2(acc);
            *(__half2*)(db + Bv.w) = gelu2(a.x, a.y);
        }
    }
    __syncthreads();

    // ---- layer 3 (K=8): idx prefetch pipeline ----
    {
        const char* sb = (const char*)(bufA + p * PADH2);
        char*       db = (char*)(bufB + p * PADH2);
        int pb = warp;
        uint4 I = __ldg(&g_i3[2 * pb + fo]);
        #pragma unroll 1
        for (; pb < NFP; pb += NW) {
            const int slot = 2 * pb + fo;
            const int pn = pb + NW;
            const int sn = (pn < NFP) ? (2 * pn + fo) : slot;
            uint4 In = __ldg(&g_i3[sn]);
            uint4 Wa = __ldg(&g_w3a[slot]);
            uint4 Wb = __ldg(&g_w3b[slot]);
            unsigned bo = __ldg(&g_b3[slot]);
            __half2 acc = __half2half2(__ushort_as_half((unsigned short)(bo & 0xFFFFu)));
            __half2 t   = __hmul2(u2h(Wa.y), LH2(I.x >> 16));
            acc = __hfma2(u2h(Wa.x), LH2(I.x & 0xFFFFu), acc);
            t   = __hfma2(u2h(Wa.w), LH2(I.y >> 16), t);
            acc = __hfma2(u2h(Wa.z), LH2(I.y & 0xFFFFu), acc);
            t   = __hfma2(u2h(Wb.y), LH2(I.z >> 16), t);
            acc = __hfma2(u2h(Wb.x), LH2(I.z & 0xFFFFu), acc);
            t   = __hfma2(u2h(Wb.w), LH2(I.w >> 16), t);
            acc = __hfma2(u2h(Wb.z), LH2(I.w & 0xFFFFu), acc);
            acc = __hadd2(acc, t);
            float2 a = __half22float2(acc);
            *(__half2*)(db + (bo >> 16)) = gelu2(a.x, a.y);
            I = In;
        }
    }
    __syncthreads();

    // --- FC partials: lane = sample; feature-packed f32x2 FMAs ---
    {
        ull acc2[NCLS];
        #pragma unroll
        for (int c = 0; c < NCLS; ++c) acc2[c] = pack2(0.0f, 0.0f);

        const __half* hB = (const __half*)bufB;
        const int sp = lane >> 1, hi = lane & 1;
        const __half* hrow = hB + sp * (PADH2 * 2) + hi;
        for (int c4 = warp; c4 < D / 4; c4 += NW) {
            const int f = c4 * 4;
            float h0 = __half2float(hrow[(f + 0) * 2]);
            float h1 = __half2float(hrow[(f + 1) * 2]);
            float h2 = __half2float(hrow[(f + 2) * 2]);
            float h3 = __half2float(hrow[(f + 3) * 2]);
            ull H01 = pack2(h0, h1);
            ull H23 = pack2(h2, h3);
            #pragma unroll
            for (int c = 0; c < NCLS; ++c) {
                float4 wv = __ldg((const float4*)(fc_w + c * D) + c4);
                ull W01 = pack2(wv.x, wv.y);
                ull W23 = pack2(wv.z, wv.w);
                FMA2(acc2[c], W01, H01, acc2[c]);
                FMA2(acc2[c], W23, H23, acc2[c]);
            }
        }
        __syncthreads();
        float* pp = part + (warp * S + lane) * NCLS;
        #pragma unroll
        for (int c = 0; c < NCLS; ++c) {
            float lo, hv; unpack2(acc2[c], lo, hv);
            pp[c] = lo + hv;
        }
    }
    __syncthreads();

    // --- stage 1 reduction: 320 threads ---
    if (tid < S * NCLS) {
        const int s = tid / NCLS;
        const int c = tid - s * NCLS;
        float sum = __ldg(fc_b + c);
        #pragma unroll
        for (int w = 0; w < NW; ++w)
            sum += part[(w * S + s) * NCLS + c];
        lgts[s * NCLS + c] = sum;
    }
    __syncthreads();

    // --- softmax ---
    if (tid < S) {
        const long gs = base + tid;
        if (gs < B) {
            float l[NCLS];
            #pragma unroll
            for (int c = 0; c < NCLS; ++c) l[c] = lgts[tid * NCLS + c];
            float m = l[0];
            #pragma unroll
            for (int c = 1; c < NCLS; ++c) m = fmaxf(m, l[c]);
            float sum = 0.0f;
            #pragma unroll
            for (int c = 0; c < NCLS; ++c) { l[c] = __expf(l[c] - m); sum += l[c]; }
            const float inv = __fdividef(1.0f, sum);
            float* o = out + gs * NCLS;
            #pragma unroll
            for (int c = 0; c < NCLS; ++c) o[c] = l[c] * inv;
        }
    }
}

extern "C" void kernel_launch(void* const* d_in, const int* in_sizes, int n_in,
                              void* d_out, int out_size)
{
    const float* x    = (const float*)d_in[0];
    const int*   idx1 = (const int*)  d_in[1];
    const float* w1   = (const float*)d_in[2];
    const float* b1   = (const float*)d_in[3];
    const int*   idx2 = (const int*)  d_in[4];
    const float* w2   = (const float*)d_in[5];
    const float* b2   = (const float*)d_in[6];
    const int*   idx3 = (const int*)  d_in[7];
    const float* w3   = (const float*)d_in[8];
    const float* b3   = (const float*)d_in[9];
    const float* fc_w = (const float*)d_in[10];
    const float* fc_b = (const float*)d_in[11];
    float* out = (float*)d_out;

    const int B = in_sizes[0] / D;
    const int grid = (B + S - 1) / S;
    const int smem_bytes = 2 * NPAIR * PADH2 * (int)sizeof(__half2);  // 100,608

    prep_rank<<<54, 32>>>(idx1, idx2, idx3);
    prep_build<<<(D + 255) / 256, 256>>>(idx1, w1, b1, idx2, w2, b2, idx3, w3, b3);

    cudaFuncSetAttribute(circnn_kernel,
                         cudaFuncAttributeMaxDynamicSharedMemorySize, smem_bytes);

    circnn_kernel<<<grid, NT, smem_bytes>>>(x, fc_w, fc_b, out, B);
}

// round 16
// speedup vs baseline: 1.0325x; 1.0325x over previous
#include <cuda_runtime.h>
#include <cuda_fp16.h>

// CircularNN R15: R14 main kernel unchanged (parity-matched pairing, S=32,
// NT=512, 2 CTAs/SM, PADH2=786, HFMA2 taps, MUFU.TANH gelu). prep_rank
// rewritten: buckets preloaded into registers (unrolled, layer-specialized)
// BEFORE the serial ballot-scan, collapsing 25 cold-LDG latencies to ~1.

#define D      784
#define PADH2  786
#define S      32
#define NPAIR  16
#define NW     16
#define NT     512
#define NCLS   10
#define NFP    392
#define NCHUNK 25     // ceil(D/32)

typedef unsigned long long ull;

// ---- packed records (slot-indexed) + prep scratch ----
__device__ uint4    g_r1[D];
__device__ uint4    g_r2a[D], g_r2b[D];
__device__ uint4    g_i3[D],  g_w3a[D], g_w3b[D];
__device__ unsigned g_b3[D];
__device__ unsigned short g_rank[3 * D];
__device__ int            g_cnt[3][2][9];

__device__ __forceinline__ unsigned duph(float w) {
    unsigned s = __half_as_ushort(__float2half_rn(w));
    return s | (s << 16);
}
__device__ __forceinline__ unsigned h16(float w) {
    return (unsigned)__half_as_ushort(__float2half_rn(w));
}
__device__ __forceinline__ __half2 u2h(unsigned u) {
    return *reinterpret_cast<const __half2*>(&u);
}

// ---- prep stage 1: ranks; buckets preloaded before the serial scan ----
__global__ void prep_rank(const int* __restrict__ idx1,
                          const int* __restrict__ idx2,
                          const int* __restrict__ idx3)
{
    const int combo = blockIdx.x;          // 0..53
    const int l   = combo / 18;
    const int rem = combo % 18;
    const int cls = rem / 9;
    const int a   = rem % 9;
    const int lane = threadIdx.x;

    int bucket[NCHUNK];
    if (l == 0) {
        #pragma unroll
        for (int i = 0; i < NCHUNK; ++i) {
            int f = i * 32 + lane;
            if (f < D) {
                int2 j = __ldg((const int2*)idx1 + f);
                bucket[i] = ((j.x & 1) == 0) + ((j.y & 1) == 0);
            } else bucket[i] = -1;
        }
    } else if (l == 1) {
        #pragma unroll
        for (int i = 0; i < NCHUNK; ++i) {
            int f = i * 32 + lane;
            if (f < D) {
                int4 j = __ldg((const int4*)idx2 + f);
                bucket[i] = ((j.x & 1) == 0) + ((j.y & 1) == 0)
                          + ((j.z & 1) == 0) + ((j.w & 1) == 0);
            } else bucket[i] = -1;
        }
    } else {
        #pragma unroll
        for (int i = 0; i < NCHUNK; ++i) {
            int f = i * 32 + lane;
            if (f < D) {
                int4 ja = __ldg((const int4*)idx3 + 2 * f);
                int4 jb = __ldg((const int4*)idx3 + 2 * f + 1);
                bucket[i] = ((ja.x & 1) == 0) + ((ja.y & 1) == 0)
                          + ((ja.z & 1) == 0) + ((ja.w & 1) == 0)
                          + ((jb.x & 1) == 0) + ((jb.y & 1) == 0)
                          + ((jb.z & 1) == 0) + ((jb.w & 1) == 0);
            } else bucket[i] = -1;
        }
    }

    int running = 0;
    #pragma unroll
    for (int i = 0; i < NCHUNK; ++i) {
        int f = i * 32 + lane;
        bool in = (bucket[i] == a) && ((f & 1) == cls);
        unsigned mask = __ballot_sync(0xffffffffu, in);
        if (in) g_rank[l * D + f] = (unsigned short)(running + __popc(mask & ((1u << lane) - 1u)));
        running += __popc(mask);
    }
    if (lane == 0) g_cnt[l][cls][a] = running;
}

// ---- prep stage 2: build slot-indexed records ----
__global__ void prep_build(const int* __restrict__ idx1, const float* __restrict__ w1, const float* __restrict__ b1,
                           const int* __restrict__ idx2, const float* __restrict__ w2, const float* __restrict__ b2,
                           const int* __restrict__ idx3, const float* __restrict__ w3, const float* __restrict__ b3)
{
    const int f = blockIdx.x * blockDim.x + threadIdx.x;
    if (f >= D) return;
    const int cls = f & 1;
    const int Ks[3] = {2, 4, 8};
    const int* idxs[3] = {idx1, idx2, idx3};

    #pragma unroll
    for (int l = 0; l < 3; ++l) {
        const int K = Ks[l];
        int a = 0;
        for (int t = 0; t < K; ++t) a += ((idxs[l][f * K + t] & 1) == 0);
        const int r = g_rank[l * D + f];

        int M[9], PB[9], LB0[9], LB1[9], Mtot = 0, lb0 = 0, lb1 = 0;
        for (int b = 0; b <= K; ++b) {
            int m = min(g_cnt[l][0][b], g_cnt[l][1][K - b]);
            M[b] = m; PB[b] = Mtot; Mtot += m;
            LB0[b] = lb0; lb0 += g_cnt[l][0][b] - m;
        }
        for (int b = 0; b <= K; ++b) {
            LB1[b] = lb1; lb1 += g_cnt[l][1][b] - M[K - b];
        }

        int q;
        if (cls == 0) {
            int m = M[a];
            q = (r < m) ? (PB[a] + r) : (Mtot + LB0[a] + (r - m));
        } else {
            int m = M[K - a];
            q = (r < m) ? (PB[K - a] + r) : (Mtot + LB1[a] + (r - m));
        }
        const int slot = 2 * q + cls;

        int ord[8];
        {
            int n = 0;
            int want = (cls == 0) ? 0 : 1;
            for (int pass = 0; pass < 2; ++pass)
                for (int t = 0; t < K; ++t) {
                    int par = idxs[l][f * K + t] & 1;
                    if (par == ((pass == 0) ? want : (want ^ 1))) ord[n++] = t;
                }
        }
        const unsigned outoff = (unsigned)(f * 4);

        if (l == 0) {
            unsigned j0 = (unsigned)idx1[2*f + ord[0]] * 4u;
            unsigned j1 = (unsigned)idx1[2*f + ord[1]] * 4u;
            uint4 rr;
            rr.x = j0 | (j1 << 16);
            rr.y = duph(w1[2*f + ord[0]]);
            rr.z = duph(w1[2*f + ord[1]]);
            rr.w = h16(b1[f]) | (outoff << 16);
            g_r1[slot] = rr;
        } else if (l == 1) {
            unsigned j[4];
            for (int t = 0; t < 4; ++t) j[t] = (unsigned)idx2[4*f + ord[t]] * 4u;
            uint4 A, Bv;
            A.x = j[0] | (j[1] << 16);
            A.y = j[2] | (j[3] << 16);
            A.z = duph(w2[4*f + ord[0]]);
            A.w = duph(w2[4*f + ord[1]]);
            Bv.x = duph(w2[4*f + ord[2]]);
            Bv.y = duph(w2[4*f + ord[3]]);
            Bv.z = duph(b2[f]);
            Bv.w = outoff;
            g_r2a[slot] = A;
            g_r2b[slot] = Bv;
        } else {
            unsigned j[8];
            for (int t = 0; t < 8; ++t) j[t] = (unsigned)idx3[8*f + ord[t]] * 4u;
            uint4 I, Wa, Wb;
            I.x = j[0] | (j[1] << 16);  I.y = j[2] | (j[3] << 16);
            I.z = j[4] | (j[5] << 16);  I.w = j[6] | (j[7] << 16);
            Wa.x = duph(w3[8*f + ord[0]]); Wa.y = duph(w3[8*f + ord[1]]);
            Wa.z = duph(w3[8*f + ord[2]]); Wa.w = duph(w3[8*f + ord[3]]);
            Wb.x = duph(w3[8*f + ord[4]]); Wb.y = duph(w3[8*f + ord[5]]);
            Wb.z = duph(w3[8*f + ord[6]]); Wb.w = duph(w3[8*f + ord[7]]);
            g_i3[slot] = I;  g_w3a[slot] = Wa;  g_w3b[slot] = Wb;
            g_b3[slot] = h16(b3[f]) | (outoff << 16);
        }
    }
}

// ---- packed f32x2 helpers ----
__device__ __forceinline__ ull pack2(float a, float b) {
    ull r; asm("mov.b64 %0, {%1, %2};" : "=l"(r) : "f"(a), "f"(b)); return r;
}
__device__ __forceinline__ void unpack2(ull v, float& a, float& b) {
    asm("mov.b64 {%0, %1}, %2;" : "=f"(a), "=f"(b) : "l"(v));
}
#define FMA2(d,a,b,c) asm("fma.rn.f32x2 %0, %1, %2, %3;" : "=l"(d) : "l"(a), "l"(b), "l"(c))
#define MUL2(d,a,b)   asm("mul.rn.f32x2 %0, %1, %2;"     : "=l"(d) : "l"(a), "l"(b))

__device__ __forceinline__ __half2 gelu2(float ax, float ay) {
    const ull C_A    = pack2(0.7978845608f, 0.7978845608f);
    const ull C_B    = pack2(0.0356774081f, 0.0356774081f);
    const ull C_HALF = pack2(0.5f, 0.5f);
    ull X = pack2(ax, ay);
    ull T; MUL2(T, X, X);
    ull V; FMA2(V, T, C_B, C_A);
    MUL2(V, V, X);
    float vx, vy; unpack2(V, vx, vy);
    float tx, ty;
    asm("tanh.approx.f32 %0, %1;" : "=f"(tx) : "f"(vx));
    asm("tanh.approx.f32 %0, %1;" : "=f"(ty) : "f"(vy));
    ull TH = pack2(tx, ty);
    ull XH; MUL2(XH, X, C_HALF);
    ull O;  FMA2(O, XH, TH, XH);
    float ox, oy; unpack2(O, ox, oy);
    return __floats2half2_rn(ox, oy);
}

#define LH2(off) (*(const __half2*)(sb + (off)))

extern __shared__ __align__(16) char smem_raw[];

__global__ __launch_bounds__(NT, 2)
void circnn_kernel(const float* __restrict__ x,
                   const float* __restrict__ fc_w, const float* __restrict__ fc_b,
                   float* __restrict__ out, int B)
{
    __half2* bufA = (__half2*)smem_raw;
    __half2* bufB = bufA + NPAIR * PADH2;
    float*   part = (float*)smem_raw;
    float*   lgts = part + NW * S * NCLS;

    const int tid  = threadIdx.x;
    const int lane = tid & 31;
    const int warp = tid >> 5;
    const int p    = lane & 15;
    const int fo   = lane >> 4;
    const long base = (long)blockIdx.x * S;

    // --- input: warp w owns sample pair w; STS.64 ---
    {
        const long s0 = base + 2 * warp;
        const float4* r0 = (const float4*)(x + s0 * (long)D);
        const float4* r1 = (const float4*)(x + (s0 + 1) * (long)D);
        uint2* drow = (uint2*)((char*)smem_raw + (warp * PADH2) * 4);
        for (int k = lane; k < D / 4; k += 32) {
            float4 a = __ldg(r0 + k);
            float4 b = __ldg(r1 + k);
            __half2 h0 = __floats2half2_rn(a.x, b.x);
            __half2 h1 = __floats2half2_rn(a.y, b.y);
            __half2 h2 = __floats2half2_rn(a.z, b.z);
            __half2 h3 = __floats2half2_rn(a.w, b.w);
            uint2 v0, v1;
            v0.x = *(unsigned*)&h0;  v0.y = *(unsigned*)&h1;
            v1.x = *(unsigned*)&h2;  v1.y = *(unsigned*)&h3;
            drow[2 * k]     = v0;
            drow[2 * k + 1] = v1;
        }
    }
    __syncthreads();

    // ---- layer 1 (K=2) ----
    {
        const char* sb = (const char*)(bufA + p * PADH2);
        char*       db = (char*)(bufB + p * PADH2);
        #pragma unroll 4
        for (int pb = warp; pb < NFP; pb += NW) {
            const int slot = 2 * pb + fo;
            uint4 r = __ldg(g_r1 + slot);
            __half2 acc = __half2half2(__ushort_as_half((unsigned short)(r.w & 0xFFFFu)));
            acc = __hfma2(u2h(r.y), LH2(r.x & 0xFFFFu), acc);
            acc = __hfma2(u2h(r.z), LH2(r.x >> 16), acc);
            float2 a = __half22float2(acc);
            *(__half2*)(db + (r.w >> 16)) = gelu2(a.x, a.y);
        }
    }
    __syncthreads();

    // ---- layer 2 (K=4) ----
    {
        const char* sb = (const char*)(bufB + p * PADH2);
        char*       db = (char*)(bufA + p * PADH2);
        #pragma unroll 4
        for (int pb = warp; pb < NFP; pb += NW) {
            const int slot = 2 * pb + fo;
            uint4 A  = __ldg(&g_r2a[slot]);
            uint4 Bv = __ldg(&g_r2b[slot]);
            __half2 acc = u2h(Bv.z);
            __half2 t   = __hmul2(u2h(A.w),  LH2(A.x >> 16));
            acc = __hfma2(u2h(A.z),  LH2(A.x & 0xFFFFu), acc);
            t   = __hfma2(u2h(Bv.y), LH2(A.y >> 16), t);
            acc = __hfma2(u2h(Bv.x), LH2(A.y & 0xFFFFu), acc);
            acc = __hadd2(acc, t);
            float2 a = __half22float2(acc);
            *(__half2*)(db + Bv.w) = gelu2(a.x, a.y);
        }
    }
    __syncthreads();

    // ---- layer 3 (K=8): idx prefetch pipeline ----
    {
        const char* sb = (const char*)(bufA + p * PADH2);
        char*       db = (char*)(bufB + p * PADH2);
        int pb = warp;
        uint4 I = __ldg(&g_i3[2 * pb + fo]);
        #pragma unroll 1
        for (; pb < NFP; pb += NW) {
            const int slot = 2 * pb + fo;
            const int pn = pb + NW;
            const int sn = (pn < NFP) ? (2 * pn + fo) : slot;
            uint4 In = __ldg(&g_i3[sn]);
            uint4 Wa = __ldg(&g_w3a[slot]);
            uint4 Wb = __ldg(&g_w3b[slot]);
            unsigned bo = __ldg(&g_b3[slot]);
            __half2 acc = __half2half2(__ushort_as_half((unsigned short)(bo & 0xFFFFu)));
            __half2 t   = __hmul2(u2h(Wa.y), LH2(I.x >> 16));
            acc = __hfma2(u2h(Wa.x), LH2(I.x & 0xFFFFu), acc);
            t   = __hfma2(u2h(Wa.w), LH2(I.y >> 16), t);
            acc = __hfma2(u2h(Wa.z), LH2(I.y & 0xFFFFu), acc);
            t   = __hfma2(u2h(Wb.y), LH2(I.z >> 16), t);
            acc = __hfma2(u2h(Wb.x), LH2(I.z & 0xFFFFu), acc);
            t   = __hfma2(u2h(Wb.w), LH2(I.w >> 16), t);
            acc = __hfma2(u2h(Wb.z), LH2(I.w & 0xFFFFu), acc);
            acc = __hadd2(acc, t);
            float2 a = __half22float2(acc);
            *(__half2*)(db + (bo >> 16)) = gelu2(a.x, a.y);
            I = In;
        }
    }
    __syncthreads();

    // --- FC partials ---
    {
        ull acc2[NCLS];
        #pragma unroll
        for (int c = 0; c < NCLS; ++c) acc2[c] = pack2(0.0f, 0.0f);

        const __half* hB = (const __half*)bufB;
        const int sp = lane >> 1, hi = lane & 1;
        const __half* hrow = hB + sp * (PADH2 * 2) + hi;
        for (int c4 = warp; c4 < D / 4; c4 += NW) {
            const int f = c4 * 4;
            float h0 = __half2float(hrow[(f + 0) * 2]);
            float h1 = __half2float(hrow[(f + 1) * 2]);
            float h2 = __half2float(hrow[(f + 2) * 2]);
            float h3 = __half2float(hrow[(f + 3) * 2]);
            ull H01 = pack2(h0, h1);
            ull H23 = pack2(h2, h3);
            #pragma unroll
            for (int c = 0; c < NCLS; ++c) {
                float4 wv = __ldg((const float4*)(fc_w + c * D) + c4);
                ull W01 = pack2(wv.x, wv.y);
                ull W23 = pack2(wv.z, wv.w);
                FMA2(acc2[c], W01, H01, acc2[c]);
                FMA2(acc2[c], W23, H23, acc2[c]);
            }
        }
        __syncthreads();
        float* pp = part + (warp * S + lane) * NCLS;
        #pragma unroll
        for (int c = 0; c < NCLS; ++c) {
            float lo, hv; unpack2(acc2[c], lo, hv);
            pp[c] = lo + hv;
        }
    }
    __syncthreads();

    // --- stage 1 reduction ---
    if (tid < S * NCLS) {
        const int s = tid / NCLS;
        const int c = tid - s * NCLS;
        float sum = __ldg(fc_b + c);
        #pragma unroll
        for (int w = 0; w < NW; ++w)
            sum += part[(w * S + s) * NCLS + c];
        lgts[s * NCLS + c] = sum;
    }
    __syncthreads();

    // --- softmax ---
    if (tid < S) {
        const long gs = base + tid;
        if (gs < B) {
            float l[NCLS];
            #pragma unroll
            for (int c = 0; c < NCLS; ++c) l[c] = lgts[tid * NCLS + c];
            float m = l[0];
            #pragma unroll
            for (int c = 1; c < NCLS; ++c) m = fmaxf(m, l[c]);
            float sum = 0.0f;
            #pragma unroll
            for (int c = 0; c < NCLS; ++c) { l[c] = __expf(l[c] - m); sum += l[c]; }
            const float inv = __fdividef(1.0f, sum);
            float* o = out + gs * NCLS;
            #pragma unroll
            for (int c = 0; c < NCLS; ++c) o[c] = l[c] * inv;
        }
    }
}

extern "C" void kernel_launch(void* const* d_in, const int* in_sizes, int n_in,
                              void* d_out, int out_size)
{
    const float* x    = (const float*)d_in[0];
    const int*   idx1 = (const int*)  d_in[1];
    const float* w1   = (const float*)d_in[2];
    const float* b1   = (const float*)d_in[3];
    const int*   idx2 = (const int*)  d_in[4];
    const float* w2   = (const float*)d_in[5];
    const float* b2   = (const float*)d_in[6];
    const int*   idx3 = (const int*)  d_in[7];
    const float* w3   = (const float*)d_in[8];
    const float* b3   = (const float*)d_in[9];
    const float* fc_w = (const float*)d_in[10];
    const float* fc_b = (const float*)d_in[11];
    float* out = (float*)d_out;

    const int B = in_sizes[0] / D;
    const int grid = (B + S - 1) / S;
    const int smem_bytes = 2 * NPAIR * PADH2 * (int)sizeof(__half2);  // 100,608

    prep_rank<<<54, 32>>>(idx1, idx2, idx3);
    prep_build<<<(D + 255) / 256, 256>>>(idx1, w1, b1, idx2, w2, b2, idx3, w3, b3);

    cudaFuncSetAttribute(circnn_kernel,
                         cudaFuncAttributeMaxDynamicSharedMemorySize, smem_bytes);

    circnn_kernel<<<grid, NT, smem_bytes>>>(x, fc_w, fc_b, out, B);
}

// round 17
// speedup vs baseline: 1.0487x; 1.0157x over previous
#include <cuda_runtime.h>
#include <cuda_fp16.h>

// CircularNN R16: main kernel unchanged (parity-matched pairing, S=32,
// NT=512, 2 CTAs/SM, PADH2=786, HFMA2 taps, MUFU.TANH gelu; stable at
// ~232.6us). Prep fused into ONE single-block kernel: smem atomic rank
// assignment (slot permutation within a bucket group does not affect
// d_out), then in-kernel prefix bases + record build. One launch, ~2-3us.

#define D      784
#define PADH2  786
#define S      32
#define NPAIR  16
#define NW     16
#define NT     512
#define NCLS   10
#define NFP    392

typedef unsigned long long ull;

// ---- packed records (slot-indexed; filled by prep kernel each launch) ----
__device__ uint4    g_r1[D];
__device__ uint4    g_r2a[D], g_r2b[D];
__device__ uint4    g_i3[D],  g_w3a[D], g_w3b[D];
__device__ unsigned g_b3[D];

__device__ __forceinline__ unsigned duph(float w) {
    unsigned s = __half_as_ushort(__float2half_rn(w));
    return s | (s << 16);
}
__device__ __forceinline__ unsigned h16(float w) {
    return (unsigned)__half_as_ushort(__float2half_rn(w));
}
__device__ __forceinline__ __half2 u2h(unsigned u) {
    return *reinterpret_cast<const __half2*>(&u);
}

// ---- fused prep: single block, 1024 threads ----
__global__ void prep_fused(const int* __restrict__ idx1, const float* __restrict__ w1, const float* __restrict__ b1,
                           const int* __restrict__ idx2, const float* __restrict__ w2, const float* __restrict__ b2,
                           const int* __restrict__ idx3, const float* __restrict__ w3, const float* __restrict__ b3)
{
    __shared__ int sCnt[3][2][9];

    const int tid = threadIdx.x;
    if (tid < 54) ((int*)sCnt)[tid] = 0;
    __syncthreads();

    const int f = tid;
    const int Ks[3] = {2, 4, 8};
    const int* idxs[3] = {idx1, idx2, idx3};

    int bucket[3], rank[3];
    if (f < D) {
        const int cls = f & 1;
        // preload taps + buckets (loads overlap)
        int2 j1v = __ldg((const int2*)idx1 + f);
        int4 j2v = __ldg((const int4*)idx2 + f);
        int4 j3a = __ldg((const int4*)idx3 + 2 * f);
        int4 j3b = __ldg((const int4*)idx3 + 2 * f + 1);
        bucket[0] = ((j1v.x & 1) == 0) + ((j1v.y & 1) == 0);
        bucket[1] = ((j2v.x & 1) == 0) + ((j2v.y & 1) == 0)
                  + ((j2v.z & 1) == 0) + ((j2v.w & 1) == 0);
        bucket[2] = ((j3a.x & 1) == 0) + ((j3a.y & 1) == 0)
                  + ((j3a.z & 1) == 0) + ((j3a.w & 1) == 0)
                  + ((j3b.x & 1) == 0) + ((j3b.y & 1) == 0)
                  + ((j3b.z & 1) == 0) + ((j3b.w & 1) == 0);
        #pragma unroll
        for (int l = 0; l < 3; ++l)
            rank[l] = atomicAdd(&sCnt[l][cls][bucket[l]], 1);
    }
    __syncthreads();

    if (f >= D) return;
    const int cls = f & 1;

    #pragma unroll
    for (int l = 0; l < 3; ++l) {
        const int K = Ks[l];
        const int a = bucket[l];
        const int r = rank[l];

        // prefix bases from final counts (redundant per-thread; <=9 iterations)
        int M[9], PB[9], LB0[9], LB1[9], Mtot = 0, lb0 = 0, lb1 = 0;
        for (int b = 0; b <= K; ++b) {
            int m = min(sCnt[l][0][b], sCnt[l][1][K - b]);
            M[b] = m; PB[b] = Mtot; Mtot += m;
            LB0[b] = lb0; lb0 += sCnt[l][0][b] - m;
        }
        for (int b = 0; b <= K; ++b) {
            LB1[b] = lb1; lb1 += sCnt[l][1][b] - M[K - b];
        }

        int q;
        if (cls == 0) {
            int m = M[a];
            q = (r < m) ? (PB[a] + r) : (Mtot + LB0[a] + (r - m));
        } else {
            int m = M[K - a];
            q = (r < m) ? (PB[K - a] + r) : (Mtot + LB1[a] + (r - m));
        }
        const int slot = 2 * q + cls;

        // ordered taps: cls0 -> even-parity first; cls1 -> odd-parity first
        int ord[8];
        {
            int n = 0;
            int want = (cls == 0) ? 0 : 1;
            for (int pass = 0; pass < 2; ++pass)
                for (int t = 0; t < K; ++t) {
                    int par = idxs[l][f * K + t] & 1;
                    if (par == ((pass == 0) ? want : (want ^ 1))) ord[n++] = t;
                }
        }
        const unsigned outoff = (unsigned)(f * 4);

        if (l == 0) {
            unsigned j0 = (unsigned)idx1[2*f + ord[0]] * 4u;
            unsigned j1 = (unsigned)idx1[2*f + ord[1]] * 4u;
            uint4 rr;
            rr.x = j0 | (j1 << 16);
            rr.y = duph(w1[2*f + ord[0]]);
            rr.z = duph(w1[2*f + ord[1]]);
            rr.w = h16(b1[f]) | (outoff << 16);
            g_r1[slot] = rr;
        } else if (l == 1) {
            unsigned j[4];
            for (int t = 0; t < 4; ++t) j[t] = (unsigned)idx2[4*f + ord[t]] * 4u;
            uint4 A, Bv;
            A.x = j[0] | (j[1] << 16);
            A.y = j[2] | (j[3] << 16);
            A.z = duph(w2[4*f + ord[0]]);
            A.w = duph(w2[4*f + ord[1]]);
            Bv.x = duph(w2[4*f + ord[2]]);
            Bv.y = duph(w2[4*f + ord[3]]);
            Bv.z = duph(b2[f]);
            Bv.w = outoff;
            g_r2a[slot] = A;
            g_r2b[slot] = Bv;
        } else {
            unsigned j[8];
            for (int t = 0; t < 8; ++t) j[t] = (unsigned)idx3[8*f + ord[t]] * 4u;
            uint4 I, Wa, Wb;
            I.x = j[0] | (j[1] << 16);  I.y = j[2] | (j[3] << 16);
            I.z = j[4] | (j[5] << 16);  I.w = j[6] | (j[7] << 16);
            Wa.x = duph(w3[8*f + ord[0]]); Wa.y = duph(w3[8*f + ord[1]]);
            Wa.z = duph(w3[8*f + ord[2]]); Wa.w = duph(w3[8*f + ord[3]]);
            Wb.x = duph(w3[8*f + ord[4]]); Wb.y = duph(w3[8*f + ord[5]]);
            Wb.z = duph(w3[8*f + ord[6]]); Wb.w = duph(w3[8*f + ord[7]]);
            g_i3[slot] = I;  g_w3a[slot] = Wa;  g_w3b[slot] = Wb;
            g_b3[slot] = h16(b3[f]) | (outoff << 16);
        }
    }
}

// ---- packed f32x2 helpers ----
__device__ __forceinline__ ull pack2(float a, float b) {
    ull r; asm("mov.b64 %0, {%1, %2};" : "=l"(r) : "f"(a), "f"(b)); return r;
}
__device__ __forceinline__ void unpack2(ull v, float& a, float& b) {
    asm("mov.b64 {%0, %1}, %2;" : "=f"(a), "=f"(b) : "l"(v));
}
#define FMA2(d,a,b,c) asm("fma.rn.f32x2 %0, %1, %2, %3;" : "=l"(d) : "l"(a), "l"(b), "l"(c))
#define MUL2(d,a,b)   asm("mul.rn.f32x2 %0, %1, %2;"     : "=l"(d) : "l"(a), "l"(b))

__device__ __forceinline__ __half2 gelu2(float ax, float ay) {
    const ull C_A    = pack2(0.7978845608f, 0.7978845608f);
    const ull C_B    = pack2(0.0356774081f, 0.0356774081f);
    const ull C_HALF = pack2(0.5f, 0.5f);
    ull X = pack2(ax, ay);
    ull T; MUL2(T, X, X);
    ull V; FMA2(V, T, C_B, C_A);
    MUL2(V, V, X);
    float vx, vy; unpack2(V, vx, vy);
    float tx, ty;
    asm("tanh.approx.f32 %0, %1;" : "=f"(tx) : "f"(vx));
    asm("tanh.approx.f32 %0, %1;" : "=f"(ty) : "f"(vy));
    ull TH = pack2(tx, ty);
    ull XH; MUL2(XH, X, C_HALF);
    ull O;  FMA2(O, XH, TH, XH);
    float ox, oy; unpack2(O, ox, oy);
    return __floats2half2_rn(ox, oy);
}

#define LH2(off) (*(const __half2*)(sb + (off)))

extern __shared__ __align__(16) char smem_raw[];

__global__ __launch_bounds__(NT, 2)
void circnn_kernel(const float* __restrict__ x,
                   const float* __restrict__ fc_w, const float* __restrict__ fc_b,
                   float* __restrict__ out, int B)
{
    __half2* bufA = (__half2*)smem_raw;
    __half2* bufB = bufA + NPAIR * PADH2;
    float*   part = (float*)smem_raw;
    float*   lgts = part + NW * S * NCLS;

    const int tid  = threadIdx.x;
    const int lane = tid & 31;
    const int warp = tid >> 5;
    const int p    = lane & 15;
    const int fo   = lane >> 4;
    const long base = (long)blockIdx.x * S;

    // --- input: warp w owns sample pair w; STS.64 ---
    {
        const long s0 = base + 2 * warp;
        const float4* r0 = (const float4*)(x + s0 * (long)D);
        const float4* r1 = (const float4*)(x + (s0 + 1) * (long)D);
        uint2* drow = (uint2*)((char*)smem_raw + (warp * PADH2) * 4);
        for (int k = lane; k < D / 4; k += 32) {
            float4 a = __ldg(r0 + k);
            float4 b = __ldg(r1 + k);
            __half2 h0 = __floats2half2_rn(a.x, b.x);
            __half2 h1 = __floats2half2_rn(a.y, b.y);
            __half2 h2 = __floats2half2_rn(a.z, b.z);
            __half2 h3 = __floats2half2_rn(a.w, b.w);
            uint2 v0, v1;
            v0.x = *(unsigned*)&h0;  v0.y = *(unsigned*)&h1;
            v1.x = *(unsigned*)&h2;  v1.y = *(unsigned*)&h3;
            drow[2 * k]     = v0;
            drow[2 * k + 1] = v1;
        }
    }
    __syncthreads();

    // ---- layer 1 (K=2) ----
    {
        const char* sb = (const char*)(bufA + p * PADH2);
        char*       db = (char*)(bufB + p * PADH2);
        #pragma unroll 4
        for (int pb = warp; pb < NFP; pb += NW) {
            const int slot = 2 * pb + fo;
            uint4 r = __ldg(g_r1 + slot);
            __half2 acc = __half2half2(__ushort_as_half((unsigned short)(r.w & 0xFFFFu)));
            acc = __hfma2(u2h(r.y), LH2(r.x & 0xFFFFu), acc);
            acc = __hfma2(u2h(r.z), LH2(r.x >> 16), acc);
            float2 a = __half22float2(acc);
            *(__half2*)(db + (r.w >> 16)) = gelu2(a.x, a.y);
        }
    }
    __syncthreads();

    // ---- layer 2 (K=4) ----
    {
        const char* sb = (const char*)(bufB + p * PADH2);
        char*       db = (char*)(bufA + p * PADH2);
        #pragma unroll 4
        for (int pb = warp; pb < NFP; pb += NW) {
            const int slot = 2 * pb + fo;
            uint4 A  = __ldg(&g_r2a[slot]);
            uint4 Bv = __ldg(&g_r2b[slot]);
            __half2 acc = u2h(Bv.z);
            __half2 t   = __hmul2(u2h(A.w),  LH2(A.x >> 16));
            acc = __hfma2(u2h(A.z),  LH2(A.x & 0xFFFFu), acc);
            t   = __hfma2(u2h(Bv.y), LH2(A.y >> 16), t);
            acc = __hfma2(u2h(Bv.x), LH2(A.y & 0xFFFFu), acc);
            acc = __hadd2(acc, t);
            float2 a = __half22float2(acc);
            *(__half2*)(db + Bv.w) = gelu2(a.x, a.y);
        }
    }
    __syncthreads();

    // ---- layer 3 (K=8): idx prefetch pipeline ----
    {
        const char* sb = (const char*)(bufA + p * PADH2);
        char*       db = (char*)(bufB + p * PADH2);
        int pb = warp;
        uint4 I = __ldg(&g_i3[2 * pb + fo]);
        #pragma unroll 1
        for (; pb < NFP; pb += NW) {
            const int slot = 2 * pb + fo;
            const int pn = pb + NW;
            const int sn = (pn < NFP) ? (2 * pn + fo) : slot;
            uint4 In = __ldg(&g_i3[sn]);
            uint4 Wa = __ldg(&g_w3a[slot]);
            uint4 Wb = __ldg(&g_w3b[slot]);
            unsigned bo = __ldg(&g_b3[slot]);
            __half2 acc = __half2half2(__ushort_as_half((unsigned short)(bo & 0xFFFFu)));
            __half2 t   = __hmul2(u2h(Wa.y), LH2(I.x >> 16));
            acc = __hfma2(u2h(Wa.x), LH2(I.x & 0xFFFFu), acc);
            t   = __hfma2(u2h(Wa.w), LH2(I.y >> 16), t);
            acc = __hfma2(u2h(Wa.z), LH2(I.y & 0xFFFFu), acc);
            t   = __hfma2(u2h(Wb.y), LH2(I.z >> 16), t);
            acc = __hfma2(u2h(Wb.x), LH2(I.z & 0xFFFFu), acc);
            t   = __hfma2(u2h(Wb.w), LH2(I.w >> 16), t);
            acc = __hfma2(u2h(Wb.z), LH2(I.w & 0xFFFFu), acc);
            acc = __hadd2(acc, t);
            float2 a = __half22float2(acc);
            *(__half2*)(db + (bo >> 16)) = gelu2(a.x, a.y);
            I = In;
        }
    }
    __syncthreads();

    // --- FC partials ---
    {
        ull acc2[NCLS];
        #pragma unroll
        for (int c = 0; c < NCLS; ++c) acc2[c] = pack2(0.0f, 0.0f);

        const __half* hB = (const __half*)bufB;
        const int sp = lane >> 1, hi = lane & 1;
        const __half* hrow = hB + sp * (PADH2 * 2) + hi;
        for (int c4 = warp; c4 < D / 4; c4 += NW) {
            const int f = c4 * 4;
            float h0 = __half2float(hrow[(f + 0) * 2]);
            float h1 = __half2float(hrow[(f + 1) * 2]);
            float h2 = __half2float(hrow[(f + 2) * 2]);
            float h3 = __half2float(hrow[(f + 3) * 2]);
            ull H01 = pack2(h0, h1);
            ull H23 = pack2(h2, h3);
            #pragma unroll
            for (int c = 0; c < NCLS; ++c) {
                float4 wv = __ldg((const float4*)(fc_w + c * D) + c4);
                ull W01 = pack2(wv.x, wv.y);
                ull W23 = pack2(wv.z, wv.w);
                FMA2(acc2[c], W01, H01, acc2[c]);
                FMA2(acc2[c], W23, H23, acc2[c]);
            }
        }
        __syncthreads();
        float* pp = part + (warp * S + lane) * NCLS;
        #pragma unroll
        for (int c = 0; c < NCLS; ++c) {
            float lo, hv; unpack2(acc2[c], lo, hv);
            pp[c] = lo + hv;
        }
    }
    __syncthreads();

    // --- stage 1 reduction ---
    if (tid < S * NCLS) {
        const int s = tid / NCLS;
        const int c = tid - s * NCLS;
        float sum = __ldg(fc_b + c);
        #pragma unroll
        for (int w = 0; w < NW; ++w)
            sum += part[(w * S + s) * NCLS + c];
        lgts[s * NCLS + c] = sum;
    }
    __syncthreads();

    // --- softmax ---
    if (tid < S) {
        const long gs = base + tid;
        if (gs < B) {
            float l[NCLS];
            #pragma unroll
            for (int c = 0; c < NCLS; ++c) l[c] = lgts[tid * NCLS + c];
            float m = l[0];
            #pragma unroll
            for (int c = 1; c < NCLS; ++c) m = fmaxf(m, l[c]);
            float sum = 0.0f;
            #pragma unroll
            for (int c = 0; c < NCLS; ++c) { l[c] = __expf(l[c] - m); sum += l[c]; }
            const float inv = __fdividef(1.0f, sum);
            float* o = out + gs * NCLS;
            #pragma unroll
            for (int c = 0; c < NCLS; ++c) o[c] = l[c] * inv;
        }
    }
}

extern "C" void kernel_launch(void* const* d_in, const int* in_sizes, int n_in,
                              void* d_out, int out_size)
{
    const float* x    = (const float*)d_in[0];
    const int*   idx1 = (const int*)  d_in[1];
    const float* w1   = (const float*)d_in[2];
    const float* b1   = (const float*)d_in[3];
    const int*   idx2 = (const int*)  d_in[4];
    const float* w2   = (const float*)d_in[5];
    const float* b2   = (const float*)d_in[6];
    const int*   idx3 = (const int*)  d_in[7];
    const float* w3   = (const float*)d_in[8];
    const float* b3   = (const float*)d_in[9];
    const float* fc_w = (const float*)d_in[10];
    const float* fc_b = (const float*)d_in[11];
    float* out = (float*)d_out;

    const int B = in_sizes[0] / D;
    const int grid = (B + S - 1) / S;
    const int smem_bytes = 2 * NPAIR * PADH2 * (int)sizeof(__half2);  // 100,608

    prep_fused<<<1, 1024>>>(idx1, w1, b1, idx2, w2, b2, idx3, w3, b3);

    cudaFuncSetAttribute(circnn_kernel,
                         cudaFuncAttributeMaxDynamicSharedMemorySize, smem_bytes);

    circnn_kernel<<<grid, NT, smem_bytes>>>(x, fc_w, fc_b, out, B);
}